// round 4
// baseline (speedup 1.0000x reference)
#include <cuda_runtime.h>

#define CONCEPTS 128
#define MM 14          // nb_mod_max + 2
#define DC 128         // concept dim
#define DIN 3

// Per-concept Gram G = W[c] W[c]^T, padded to 8 floats: {G00,G01,G02,G11,G12,G22,_,_}
__device__ float g_G[CONCEPTS * 8];

__global__ void gmat_kernel(const float* __restrict__ W) {
    int c = blockIdx.x;
    int lane = threadIdx.x;
    const float4* w = reinterpret_cast<const float4*>(W + (size_t)c * DIN * DC);
    float4 a = w[lane];
    float4 b = w[32 + lane];
    float4 d = w[64 + lane];
    float s[6];
    s[0] = a.x*a.x + a.y*a.y + a.z*a.z + a.w*a.w;
    s[1] = a.x*b.x + a.y*b.y + a.z*b.z + a.w*b.w;
    s[2] = a.x*d.x + a.y*d.y + a.z*d.z + a.w*d.w;
    s[3] = b.x*b.x + b.y*b.y + b.z*b.z + b.w*b.w;
    s[4] = b.x*d.x + b.y*d.y + b.z*d.z + b.w*d.w;
    s[5] = d.x*d.x + d.y*d.y + d.z*d.z + d.w*d.w;
    #pragma unroll
    for (int off = 16; off; off >>= 1)
        #pragma unroll
        for (int k = 0; k < 6; k++)
            s[k] += __shfl_xor_sync(0xffffffffu, s[k], off);
    if (lane == 0) {
        #pragma unroll
        for (int k = 0; k < 6; k++) g_G[c * 8 + k] = s[k];
        g_G[c * 8 + 6] = 0.0f;
        g_G[c * 8 + 7] = 0.0f;
    }
}

// ---------------------------------------------------------------------------
// 4 rows per warp = 2 pairs; within a pair, 16 lanes per row.
// All gathers for both pairs issue before any reduction; the two pairs'
// butterfly chains are interleaved so SHFL latency of one overlaps loads /
// shfls of the other.
// ---------------------------------------------------------------------------
__global__ void __launch_bounds__(256) impact_kernel(
    const int*   __restrict__ user_ids,
    const int*   __restrict__ item_ids,
    const int*   __restrict__ concept_ids,
    const float* __restrict__ uemb,     // (USER_N, 128)
    const float* __restrict__ irw,      // (ITEM_N*14, 3)
    const float* __restrict__ W,        // (128, 3, 128)
    const float* __restrict__ maskt,    // (ITEM_N, 14)
    const int*   __restrict__ nbmod,    // (ITEM_N,)
    float*       __restrict__ out,
    int nrows)
{
    const unsigned FULL = 0xffffffffu;
    int warp = (int)((blockIdx.x * blockDim.x + threadIdx.x) >> 5);
    int lane = threadIdx.x & 31;
    int half = lane >> 4;
    int hl   = lane & 15;

    long base = (long)warp * 4;
    long rowA = base + half;        // pair A rows: base+0, base+1
    long rowB = base + 2 + half;    // pair B rows: base+2, base+3
    bool actA = rowA < nrows;
    bool actB = rowB < nrows;
    long riA = actA ? rowA : 0;
    long riB = actB ? rowB : 0;

    // ---- ids for both pairs ----
    int uA = user_ids[riA],   uB = user_ids[riB];
    int iA = item_ids[riA],   iB = item_ids[riB];
    int cA = concept_ids[riA], cB = concept_ids[riB];

    // ---- gathers: u + W for both pairs (16 LDG.128 in flight) ----
    const float* ubA = uemb + (size_t)uA * DC;
    const float* ubB = uemb + (size_t)uB * DC;
    float4 uaA = *reinterpret_cast<const float4*>(ubA + 4 * hl);
    float4 ucA = *reinterpret_cast<const float4*>(ubA + 64 + 4 * hl);
    float4 uaB = *reinterpret_cast<const float4*>(ubB + 4 * hl);
    float4 ucB = *reinterpret_cast<const float4*>(ubB + 64 + 4 * hl);

    const float* wbA = W + (size_t)cA * DIN * DC;
    const float* wbB = W + (size_t)cB * DIN * DC;
    float4 w0aA = *reinterpret_cast<const float4*>(wbA + 4 * hl);
    float4 w0bA = *reinterpret_cast<const float4*>(wbA + 64 + 4 * hl);
    float4 w1aA = *reinterpret_cast<const float4*>(wbA + DC + 4 * hl);
    float4 w1bA = *reinterpret_cast<const float4*>(wbA + DC + 64 + 4 * hl);
    float4 w2aA = *reinterpret_cast<const float4*>(wbA + 2 * DC + 4 * hl);
    float4 w2bA = *reinterpret_cast<const float4*>(wbA + 2 * DC + 64 + 4 * hl);
    float4 w0aB = *reinterpret_cast<const float4*>(wbB + 4 * hl);
    float4 w0bB = *reinterpret_cast<const float4*>(wbB + 64 + 4 * hl);
    float4 w1aB = *reinterpret_cast<const float4*>(wbB + DC + 4 * hl);
    float4 w1bB = *reinterpret_cast<const float4*>(wbB + DC + 64 + 4 * hl);
    float4 w2aB = *reinterpret_cast<const float4*>(wbB + 2 * DC + 4 * hl);
    float4 w2bB = *reinterpret_cast<const float4*>(wbB + 2 * DC + 64 + 4 * hl);

    // ---- item-side loads (depend only on item id; issue early) ----
    float e0A = 0.f, e1A = 0.f, e2A = 0.f, mA = 0.f;
    float e0B = 0.f, e1B = 0.f, e2B = 0.f, mB = 0.f;
    if (hl < MM) {
        const float* eA = irw + ((size_t)iA * MM + hl) * DIN;
        const float* eB = irw + ((size_t)iB * MM + hl) * DIN;
        e0A = eA[0]; e1A = eA[1]; e2A = eA[2];
        e0B = eB[0]; e1B = eB[1]; e2B = eB[2];
        mA = maskt[(size_t)iA * MM + hl];
        mB = maskt[(size_t)iB * MM + hl];
    }
    const float4* GpA = reinterpret_cast<const float4*>(g_G + cA * 8);
    const float4* GpB = reinterpret_cast<const float4*>(g_G + cB * 8);
    float4 GaA = __ldg(GpA), GbA = __ldg(GpA + 1);
    float4 GaB = __ldg(GpB), GbB = __ldg(GpB + 1);

    // ---- partial dots ----
    float v0A = uaA.x*w0aA.x + uaA.y*w0aA.y + uaA.z*w0aA.z + uaA.w*w0aA.w
              + ucA.x*w0bA.x + ucA.y*w0bA.y + ucA.z*w0bA.z + ucA.w*w0bA.w;
    float v1A = uaA.x*w1aA.x + uaA.y*w1aA.y + uaA.z*w1aA.z + uaA.w*w1aA.w
              + ucA.x*w1bA.x + ucA.y*w1bA.y + ucA.z*w1bA.z + ucA.w*w1bA.w;
    float v2A = uaA.x*w2aA.x + uaA.y*w2aA.y + uaA.z*w2aA.z + uaA.w*w2aA.w
              + ucA.x*w2bA.x + ucA.y*w2bA.y + ucA.z*w2bA.z + ucA.w*w2bA.w;
    float v0B = uaB.x*w0aB.x + uaB.y*w0aB.y + uaB.z*w0aB.z + uaB.w*w0aB.w
              + ucB.x*w0bB.x + ucB.y*w0bB.y + ucB.z*w0bB.z + ucB.w*w0bB.w;
    float v1B = uaB.x*w1aB.x + uaB.y*w1aB.y + uaB.z*w1aB.z + uaB.w*w1aB.w
              + ucB.x*w1bB.x + ucB.y*w1bB.y + ucB.z*w1bB.z + ucB.w*w1bB.w;
    float v2B = uaB.x*w2aB.x + uaB.y*w2aB.y + uaB.z*w2aB.z + uaB.w*w2aB.w
              + ucB.x*w2bB.x + ucB.y*w2bB.y + ucB.z*w2bB.z + ucB.w*w2bB.w;

    // ---- interleaved butterfly all-reduce within 16-lane halves ----
    #pragma unroll
    for (int off = 8; off; off >>= 1) {
        v0A += __shfl_xor_sync(FULL, v0A, off);
        v0B += __shfl_xor_sync(FULL, v0B, off);
        v1A += __shfl_xor_sync(FULL, v1A, off);
        v1B += __shfl_xor_sync(FULL, v1B, off);
        v2A += __shfl_xor_sync(FULL, v2A, off);
        v2B += __shfl_xor_sync(FULL, v2B, off);
    }

    // ---- scores ----
    float sA = __int_as_float(0x7f800000);
    float sB = __int_as_float(0x7f800000);
    if (hl < MM) {
        float qA = e0A*e0A*GaA.x + e1A*e1A*GaA.w + e2A*e2A*GbA.y
                 + 2.0f*(e0A*e1A*GaA.y + e0A*e2A*GaA.z + e1A*e2A*GbA.x);
        sA = qA - 2.0f*(e0A*v0A + e1A*v1A + e2A*v2A) + mA;
        float qB = e0B*e0B*GaB.x + e1B*e1B*GaB.w + e2B*e2B*GbB.y
                 + 2.0f*(e0B*e1B*GaB.y + e0B*e2B*GaB.z + e1B*e2B*GbB.x);
        sB = qB - 2.0f*(e0B*v0B + e1B*v1B + e2B*v2B) + mB;
    }

    // ---- interleaved lexicographic argmin within halves ----
    int biA = hl, biB = hl;
    #pragma unroll
    for (int off = 8; off; off >>= 1) {
        float ovA = __shfl_xor_sync(FULL, sA, off);
        int   oiA = __shfl_xor_sync(FULL, biA, off);
        float ovB = __shfl_xor_sync(FULL, sB, off);
        int   oiB = __shfl_xor_sync(FULL, biB, off);
        if (ovA < sA || (ovA == sA && oiA < biA)) { sA = ovA; biA = oiA; }
        if (ovB < sB || (ovB == sB && oiB < biB)) { sB = ovB; biB = oiB; }
    }

    if (hl == 0) {
        if (actA) {
            float nb = (float)nbmod[iA];
            out[rowA] = ((float)biA - 1.0f) / (nb - 1.0f) + 1.0f;
        }
        if (actB) {
            float nb = (float)nbmod[iB];
            out[rowB] = ((float)biB - 1.0f) / (nb - 1.0f) + 1.0f;
        }
    }
}

extern "C" void kernel_launch(void* const* d_in, const int* in_sizes, int n_in,
                              void* d_out, int out_size) {
    const int*   user_ids    = (const int*)  d_in[0];
    const int*   item_ids    = (const int*)  d_in[1];
    const int*   concept_ids = (const int*)  d_in[2];
    const float* uemb        = (const float*)d_in[3];
    const float* irw         = (const float*)d_in[4];
    const float* W           = (const float*)d_in[5];
    const float* maskt       = (const float*)d_in[6];
    const int*   nbmod       = (const int*)  d_in[7];
    float* out = (float*)d_out;
    int nrows = in_sizes[0];

    gmat_kernel<<<CONCEPTS, 32>>>(W);

    int warps = (nrows + 3) / 4;          // 4 rows per warp
    int blocks = (warps + 7) / 8;         // 256 threads = 8 warps
    impact_kernel<<<blocks, 256>>>(
        user_ids, item_ids, concept_ids, uemb, irw, W, maskt, nbmod, out, nrows);
}